// round 15
// baseline (speedup 1.0000x reference)
#include <cuda_runtime.h>
#include <cstdint>

#define NMAX 200000
#define EMAX 6400000
#define CHUNK 2048
#define NCHUNKS ((NMAX + CHUNK - 1) / CHUNK)   // 98
#define GT 64   // gemm tile nodes

// Scratch (device globals — no allocation allowed)
__device__ int g_deg[NMAX];
__device__ int g_rowoff[NMAX];
__device__ int g_cursor[NMAX];
__device__ int g_partial[NCHUNKS];
__device__ int g_flag[NCHUNKS];      // zeroed by memset each launch (replay-safe)
__device__ int g_csr[EMAX];
__device__ __align__(16) float g_dinv[NMAX];
__device__ __align__(16) float g_tmpA[NMAX * 4];
__device__ __align__(16) float g_tmpB[NMAX * 4];
__device__ __align__(16) float g_tmpC[NMAX * 2];

static inline int cdiv(int a, int b) { return (a + b - 1) / b; }

// ============ merged K1: gemm role (3/5 of blocks) + count role (2/5) ============
__global__ void __launch_bounds__(128)
gemm_count_kernel(const float* __restrict__ x, const float* __restrict__ W,
                  const int* __restrict__ dst, int n, int e, int ntiles) {
    __shared__ float4 Wv[128];
    __shared__ float4 xs[GT * 33];
    __shared__ float4 ps[GT];

    int bid = blockIdx.x;
    int t = threadIdx.x;
    int r5 = bid % 5;

    if (r5 >= 3) {
        // ---- count role (2 of every 5 blocks) ----
        int cidx = (bid / 5) * 2 + (r5 - 3);
        int CB = (gridDim.x / 5) * 2;
        int quads = e >> 2;
        for (int q = cidx * 128 + t; q < quads; q += CB * 128) {
            int4 d4 = __ldg((const int4*)dst + q);
            atomicAdd(&g_deg[d4.x], 1);
            atomicAdd(&g_deg[d4.y], 1);
            atomicAdd(&g_deg[d4.z], 1);
            atomicAdd(&g_deg[d4.w], 1);
        }
        if (cidx == 0 && t == 0)
            for (int i = quads * 4; i < e; i++) atomicAdd(&g_deg[dst[i]], 1);
        return;
    }

    // ---- gemm role (3 of every 5 blocks) ----
    int tile = (bid / 5) * 3 + r5;
    if (tile >= ntiles) return;
    if (t < 128) Wv[t] = ((const float4*)W)[t];
    int node0 = tile * GT;
    int nn = min(GT, n - node0);
    int tot = nn * 32;
    const float4* x4 = (const float4*)x;
    for (int idx = t; idx < tot; idx += 128) {
        int nd = idx >> 5, kq = idx & 31;
        xs[nd * 33 + kq] = x4[(size_t)(node0 + nd) * 32 + kq];
    }
    __syncthreads();
    int half = t >> 6;
    int node = t & 63;
    float4 acc = make_float4(0.f, 0.f, 0.f, 0.f);
    if (node < nn) {
        int k0 = half * 16;
        #pragma unroll
        for (int kq = 0; kq < 16; kq++) {
            float4 xv = xs[node * 33 + k0 + kq];
            float4 w0 = Wv[(k0 + kq) * 4 + 0];
            float4 w1 = Wv[(k0 + kq) * 4 + 1];
            float4 w2 = Wv[(k0 + kq) * 4 + 2];
            float4 w3 = Wv[(k0 + kq) * 4 + 3];
            acc.x += xv.x * w0.x + xv.y * w1.x + xv.z * w2.x + xv.w * w3.x;
            acc.y += xv.x * w0.y + xv.y * w1.y + xv.z * w2.y + xv.w * w3.y;
            acc.z += xv.x * w0.z + xv.y * w1.z + xv.z * w2.z + xv.w * w3.z;
            acc.w += xv.x * w0.w + xv.y * w1.w + xv.z * w2.w + xv.w * w3.w;
        }
    }
    if (half == 1) ps[node] = acc;
    __syncthreads();
    if (half == 0 && node < nn) {
        float4 b = ps[node];
        int i = node0 + node;
        *(float4*)(g_tmpA + (size_t)i * 4) =
            make_float4(acc.x + b.x, acc.y + b.y, acc.z + b.z, acc.w + b.w);
    }
}

// fallbacks (misaligned edge array)
__global__ void count_deg_scalar_kernel(const int* __restrict__ dst, int e) {
    int i = blockIdx.x * blockDim.x + threadIdx.x;
    if (i < e) atomicAdd(&g_deg[dst[i]], 1);
}
__global__ void gemm1_plain_kernel(const float* __restrict__ x, const float* __restrict__ W, int n) {
    __shared__ float4 Wv[128];
    __shared__ float4 xs[GT * 33];
    __shared__ float4 ps[GT];
    int t = threadIdx.x;
    if (t < 128) Wv[t] = ((const float4*)W)[t];
    int node0 = blockIdx.x * GT;
    int nn = min(GT, n - node0);
    int tot = nn * 32;
    const float4* x4 = (const float4*)x;
    for (int idx = t; idx < tot; idx += 128) {
        int nd = idx >> 5, kq = idx & 31;
        xs[nd * 33 + kq] = x4[(size_t)(node0 + nd) * 32 + kq];
    }
    __syncthreads();
    int half = t >> 6;
    int node = t & 63;
    float4 acc = make_float4(0.f, 0.f, 0.f, 0.f);
    if (node < nn) {
        int k0 = half * 16;
        #pragma unroll
        for (int kq = 0; kq < 16; kq++) {
            float4 xv = xs[node * 33 + k0 + kq];
            float4 w0 = Wv[(k0 + kq) * 4 + 0];
            float4 w1 = Wv[(k0 + kq) * 4 + 1];
            float4 w2 = Wv[(k0 + kq) * 4 + 2];
            float4 w3 = Wv[(k0 + kq) * 4 + 3];
            acc.x += xv.x * w0.x + xv.y * w1.x + xv.z * w2.x + xv.w * w3.x;
            acc.y += xv.x * w0.y + xv.y * w1.y + xv.z * w2.y + xv.w * w3.y;
            acc.z += xv.x * w0.z + xv.y * w1.z + xv.z * w2.z + xv.w * w3.z;
            acc.w += xv.x * w0.w + xv.y * w1.w + xv.z * w2.w + xv.w * w3.w;
        }
    }
    if (half == 1) ps[node] = acc;
    __syncthreads();
    if (half == 0 && node < nn) {
        float4 b = ps[node];
        int i = node0 + node;
        *(float4*)(g_tmpA + (size_t)i * 4) =
            make_float4(acc.x + b.x, acc.y + b.y, acc.z + b.z, acc.w + b.w);
    }
}

// ---------------- scanAC: single-pass chunk scan with decoupled lookback ----------------
// Also: apply offsets + dinv + cursor + prescale tmpA. flags zeroed per launch.
__global__ void __launch_bounds__(256)
scanAC_kernel(int n, int nchunks) {
    __shared__ int sdeg[CHUNK];
    __shared__ int wsum[8], woff[8];
    __shared__ int s_off;
    int t = threadIdx.x;
    int blk = blockIdx.x;
    int c0 = blk * CHUNK;

    // coalesced stage of this chunk's degrees
    #pragma unroll
    for (int r = 0; r < CHUNK / 256; r++) {
        int idx = t + r * 256;
        int node = c0 + idx;
        sdeg[idx] = (node < n) ? g_deg[node] : 0;
    }
    __syncthreads();

    // local exclusive scan (thread = 8 contiguous entries)
    int s = 0;
    #pragma unroll
    for (int r = 0; r < 8; r++) s += sdeg[t * 8 + r];
    int lane = t & 31, wid = t >> 5;
    int incl = s;
    #pragma unroll
    for (int off = 1; off < 32; off <<= 1) {
        int v = __shfl_up_sync(0xffffffffu, incl, off);
        if (lane >= off) incl += v;
    }
    if (lane == 31) wsum[wid] = incl;
    __syncthreads();
    if (t < 8) {
        int acc = 0;
        for (int w = 0; w < t; w++) acc += wsum[w];
        woff[t] = acc;
    }
    __syncthreads();
    int total = woff[7] + wsum[7];

    // publish partial (release)
    if (t == 0) {
        g_partial[blk] = total;
        __threadfence();
        atomicExch(&g_flag[blk], 1);
    }

    // lookback: 32 lanes cooperatively sum all predecessor partials
    if (wid == 0) {
        int acc = 0;
        for (int b0 = lane; b0 < blk; b0 += 32) {
            while (atomicAdd(&g_flag[b0], 0) == 0) __nanosleep(32);
            acc += g_partial[b0];
        }
        #pragma unroll
        for (int off = 16; off > 0; off >>= 1)
            acc += __shfl_down_sync(0xffffffffu, acc, off);
        if (lane == 0) s_off = acc;
    }
    __syncthreads();
    int base = s_off;

    // apply: rowoff/cursor/dinv/prescale
    int run = incl - s + woff[wid] + base;
    #pragma unroll
    for (int r = 0; r < 8; r++) {
        int node = c0 + t * 8 + r;
        if (node < n) {
            g_rowoff[node] = run;
            g_cursor[node] = run;
            run += sdeg[t * 8 + r];
        }
    }
    __syncthreads();
    // dinv + prescale (coalesced over chunk)
    #pragma unroll
    for (int r = 0; r < CHUNK / 256; r++) {
        int node = c0 + t + r * 256;
        if (node < n) {
            float dv = rsqrtf((float)(sdeg[t + r * 256] + 1));  // +1 self-loop
            g_dinv[node] = dv;
            float4 v = *(const float4*)(g_tmpA + (size_t)node * 4);
            v.x *= dv; v.y *= dv; v.z *= dv; v.w *= dv;
            *(float4*)(g_tmpA + (size_t)node * 4) = v;
        }
    }
}

// ---------------- scatter: 4 edges/thread (measured-best shape) ----------------
__global__ void scatter_kernel(const int* __restrict__ src, const int* __restrict__ dst, int e) {
    int t = blockIdx.x * blockDim.x + threadIdx.x;
    int base = t * 4;
    if (base >= e) return;
    if (base + 4 <= e) {
        int4 s4 = *(const int4*)(src + base);
        int4 d4 = *(const int4*)(dst + base);
        int p;
        p = atomicAdd(&g_cursor[d4.x], 1); g_csr[p] = s4.x;
        p = atomicAdd(&g_cursor[d4.y], 1); g_csr[p] = s4.y;
        p = atomicAdd(&g_cursor[d4.z], 1); g_csr[p] = s4.z;
        p = atomicAdd(&g_cursor[d4.w], 1); g_csr[p] = s4.w;
    } else {
        for (int i = base; i < e; i++) {
            int p = atomicAdd(&g_cursor[dst[i]], 1);
            g_csr[p] = src[i];
        }
    }
}
__global__ void scatter_scalar_kernel(const int* __restrict__ src, const int* __restrict__ dst, int e) {
    int i = blockIdx.x * blockDim.x + threadIdx.x;
    if (i >= e) return;
    int p = atomicAdd(&g_cursor[dst[i]], 1);
    g_csr[p] = src[i];
}

// ========= fused pull (FIN=4): unroll 8, high occupancy =========
template <int FNEXT>
__global__ void __launch_bounds__(256, 6)
pull4_kernel(const float* __restrict__ tin,
             const float* __restrict__ b,
             const float* __restrict__ Wn,
             float* __restrict__ tout, int n) {
    int i = blockIdx.x * blockDim.x + threadIdx.x;
    if (i >= n) return;
    const float4* tp = (const float4*)tin;
    float4 a0 = tp[i];  // self-loop term (prescaled)
    float4 a1 = make_float4(0.f, 0.f, 0.f, 0.f), a2 = a1, a3 = a1;
    int j = g_rowoff[i];
    int jend = j + g_deg[i];
    for (; j + 8 <= jend; j += 8) {
        int s0 = __ldg(&g_csr[j]),     s1 = __ldg(&g_csr[j + 1]);
        int s2 = __ldg(&g_csr[j + 2]), s3 = __ldg(&g_csr[j + 3]);
        int s4 = __ldg(&g_csr[j + 4]), s5 = __ldg(&g_csr[j + 5]);
        int s6 = __ldg(&g_csr[j + 6]), s7 = __ldg(&g_csr[j + 7]);
        float4 v0 = tp[s0], v1 = tp[s1], v2 = tp[s2], v3 = tp[s3];
        float4 v4 = tp[s4], v5 = tp[s5], v6 = tp[s6], v7 = tp[s7];
        a0.x += v0.x; a0.y += v0.y; a0.z += v0.z; a0.w += v0.w;
        a1.x += v1.x; a1.y += v1.y; a1.z += v1.z; a1.w += v1.w;
        a2.x += v2.x; a2.y += v2.y; a2.z += v2.z; a2.w += v2.w;
        a3.x += v3.x; a3.y += v3.y; a3.z += v3.z; a3.w += v3.w;
        a0.x += v4.x; a0.y += v4.y; a0.z += v4.z; a0.w += v4.w;
        a1.x += v5.x; a1.y += v5.y; a1.z += v5.z; a1.w += v5.w;
        a2.x += v6.x; a2.y += v6.y; a2.z += v6.z; a2.w += v6.w;
        a3.x += v7.x; a3.y += v7.y; a3.z += v7.z; a3.w += v7.w;
    }
    for (; j < jend; j++) {
        float4 v = tp[__ldg(&g_csr[j])];
        a0.x += v.x; a0.y += v.y; a0.z += v.z; a0.w += v.w;
    }
    float dv = g_dinv[i];
    float sx = (a0.x + a1.x) + (a2.x + a3.x);
    float sy = (a0.y + a1.y) + (a2.y + a3.y);
    float sz = (a0.z + a1.z) + (a2.z + a3.z);
    float sw = (a0.w + a1.w) + (a2.w + a3.w);
    float h0 = tanhf(sx * dv + __ldg(&b[0]));
    float h1 = tanhf(sy * dv + __ldg(&b[1]));
    float h2 = tanhf(sz * dv + __ldg(&b[2]));
    float h3 = tanhf(sw * dv + __ldg(&b[3]));
    if (FNEXT == 4) {
        float4 o;
        o.x = (h0*__ldg(&Wn[0*4+0]) + h1*__ldg(&Wn[1*4+0]) + h2*__ldg(&Wn[2*4+0]) + h3*__ldg(&Wn[3*4+0])) * dv;
        o.y = (h0*__ldg(&Wn[0*4+1]) + h1*__ldg(&Wn[1*4+1]) + h2*__ldg(&Wn[2*4+1]) + h3*__ldg(&Wn[3*4+1])) * dv;
        o.z = (h0*__ldg(&Wn[0*4+2]) + h1*__ldg(&Wn[1*4+2]) + h2*__ldg(&Wn[2*4+2]) + h3*__ldg(&Wn[3*4+2])) * dv;
        o.w = (h0*__ldg(&Wn[0*4+3]) + h1*__ldg(&Wn[1*4+3]) + h2*__ldg(&Wn[2*4+3]) + h3*__ldg(&Wn[3*4+3])) * dv;
        *(float4*)(tout + (size_t)i * 4) = o;
    } else {
        float2 o;
        o.x = (h0*__ldg(&Wn[0*2+0]) + h1*__ldg(&Wn[1*2+0]) + h2*__ldg(&Wn[2*2+0]) + h3*__ldg(&Wn[3*2+0])) * dv;
        o.y = (h0*__ldg(&Wn[0*2+1]) + h1*__ldg(&Wn[1*2+1]) + h2*__ldg(&Wn[2*2+1]) + h3*__ldg(&Wn[3*2+1])) * dv;
        *(float2*)(tout + (size_t)i * 2) = o;
    }
}

// ========= fused pull (FIN=2) + classifier + outputs =========
__global__ void __launch_bounds__(256, 6)
pull2_cls_kernel(const float* __restrict__ tin,
                 const float* __restrict__ b3,
                 const float* __restrict__ Wc,
                 const float* __restrict__ bc,
                 float* __restrict__ out,
                 float* __restrict__ hsec, int n) {
    int i = blockIdx.x * blockDim.x + threadIdx.x;
    if (i >= n) return;
    const float2* tp = (const float2*)tin;
    float2 a0 = tp[i];
    float2 a1 = make_float2(0.f, 0.f), a2 = a1, a3 = a1;
    int j = g_rowoff[i];
    int jend = j + g_deg[i];
    for (; j + 8 <= jend; j += 8) {
        int s0 = __ldg(&g_csr[j]),     s1 = __ldg(&g_csr[j + 1]);
        int s2 = __ldg(&g_csr[j + 2]), s3 = __ldg(&g_csr[j + 3]);
        int s4 = __ldg(&g_csr[j + 4]), s5 = __ldg(&g_csr[j + 5]);
        int s6 = __ldg(&g_csr[j + 6]), s7 = __ldg(&g_csr[j + 7]);
        float2 v0 = tp[s0], v1 = tp[s1], v2 = tp[s2], v3 = tp[s3];
        float2 v4 = tp[s4], v5 = tp[s5], v6 = tp[s6], v7 = tp[s7];
        a0.x += v0.x; a0.y += v0.y;
        a1.x += v1.x; a1.y += v1.y;
        a2.x += v2.x; a2.y += v2.y;
        a3.x += v3.x; a3.y += v3.y;
        a0.x += v4.x; a0.y += v4.y;
        a1.x += v5.x; a1.y += v5.y;
        a2.x += v6.x; a2.y += v6.y;
        a3.x += v7.x; a3.y += v7.y;
    }
    for (; j < jend; j++) {
        float2 v = tp[__ldg(&g_csr[j])];
        a0.x += v.x; a0.y += v.y;
    }
    float dv = g_dinv[i];
    float sx = (a0.x + a1.x) + (a2.x + a3.x);
    float sy = (a0.y + a1.y) + (a2.y + a3.y);
    float h0 = tanhf(sx * dv + __ldg(&b3[0]));
    float h1 = tanhf(sy * dv + __ldg(&b3[1]));
    *(float2*)(hsec + (size_t)i * 2) = make_float2(h0, h1);
    #pragma unroll
    for (int j0 = 0; j0 < 16; j0 += 4) {
        float4 v;
        v.x = h0*__ldg(&Wc[0*16+j0+0]) + h1*__ldg(&Wc[1*16+j0+0]) + __ldg(&bc[j0+0]);
        v.y = h0*__ldg(&Wc[0*16+j0+1]) + h1*__ldg(&Wc[1*16+j0+1]) + __ldg(&bc[j0+1]);
        v.z = h0*__ldg(&Wc[0*16+j0+2]) + h1*__ldg(&Wc[1*16+j0+2]) + __ldg(&bc[j0+2]);
        v.w = h0*__ldg(&Wc[0*16+j0+3]) + h1*__ldg(&Wc[1*16+j0+3]) + __ldg(&bc[j0+3]);
        *(float4*)(out + (size_t)i * 16 + j0) = v;
    }
}

extern "C" void kernel_launch(void* const* d_in, const int* in_sizes, int n_in,
                              void* d_out, int out_size) {
    const float* x  = (const float*)d_in[0];
    const float* W1 = (const float*)d_in[1];
    const float* b1 = (const float*)d_in[2];
    const float* W2 = (const float*)d_in[3];
    const float* b2 = (const float*)d_in[4];
    const float* W3 = (const float*)d_in[5];
    const float* b3 = (const float*)d_in[6];
    const float* Wc = (const float*)d_in[7];
    const float* bc = (const float*)d_in[8];
    const int*   ei = (const int*)d_in[9];

    const int n = in_sizes[0] / 128;
    const int e = in_sizes[9] / 2;
    const int* src = ei;
    const int* dst = ei + e;

    const int B = 256;
    const bool vec = ((e & 3) == 0) &&
                     ((((unsigned long long)(uintptr_t)dst) & 15ull) == 0) &&
                     ((((unsigned long long)(uintptr_t)src) & 15ull) == 0);

    int*   deg_p;   cudaGetSymbolAddress((void**)&deg_p, g_deg);
    int*   flag_p;  cudaGetSymbolAddress((void**)&flag_p, g_flag);
    float* tmpA;    cudaGetSymbolAddress((void**)&tmpA, g_tmpA);
    float* tmpB;    cudaGetSymbolAddress((void**)&tmpB, g_tmpB);
    float* tmpC;    cudaGetSymbolAddress((void**)&tmpC, g_tmpC);

    cudaMemsetAsync(deg_p, 0, (size_t)n * sizeof(int));
    cudaMemsetAsync(flag_p, 0, NCHUNKS * sizeof(int));

    const int ntiles = cdiv(n, GT);
    if (vec) {
        int T = cdiv(ntiles, 3) * 5;   // 3 gemm : 2 count per 5 blocks
        gemm_count_kernel<<<T, 128>>>(x, W1, dst, n, e, ntiles);
    } else {
        gemm1_plain_kernel<<<ntiles, 128>>>(x, W1, n);
        count_deg_scalar_kernel<<<cdiv(e, B), B>>>(dst, e);
    }

    // single-pass scan + apply + dinv + prescale
    scanAC_kernel<<<cdiv(n, CHUNK), 256>>>(n, cdiv(n, CHUNK));

    if (vec) scatter_kernel<<<cdiv(cdiv(e, 4), B), B>>>(src, dst, e);
    else     scatter_scalar_kernel<<<cdiv(e, B), B>>>(src, dst, e);

    pull4_kernel<4><<<cdiv(n, B), B>>>(tmpA, b1, W2, tmpB, n);
    pull4_kernel<2><<<cdiv(n, B), B>>>(tmpB, b2, W3, tmpC, n);

    float* out  = (float*)d_out;
    float* hsec = out + (size_t)n * 16;
    pull2_cls_kernel<<<cdiv(n, B), B>>>(tmpC, b3, Wc, bc, out, hsec, n);
}

// round 16
// speedup vs baseline: 1.0274x; 1.0274x over previous
#include <cuda_runtime.h>
#include <cstdint>

#define NMAX 200000
#define EMAX 6400000
#define CHUNK 2048
#define NCHUNKS ((NMAX + CHUNK - 1) / CHUNK)   // 98

// Scratch (device globals — no allocation allowed)
__device__ int g_deg[NMAX];
__device__ int g_rowoff[NMAX];
__device__ int g_cursor[NMAX];
__device__ int g_csum[NCHUNKS];
__device__ int g_csr[EMAX];
__device__ __align__(16) float g_dinv[NMAX];
__device__ __align__(16) float g_tmpA[NMAX * 4];
__device__ __align__(16) float g_tmpB[NMAX * 4];
__device__ __align__(16) float g_tmpC[NMAX * 2];

static inline int cdiv(int a, int b) { return (a + b - 1) / b; }

// ---------------- count: full grid, 4 edges/thread ----------------
__global__ void count_deg_kernel(const int* __restrict__ dst, int e) {
    int t = blockIdx.x * blockDim.x + threadIdx.x;
    int base = t * 4;
    if (base >= e) return;
    if (base + 4 <= e) {
        int4 d4 = *(const int4*)(dst + base);
        atomicAdd(&g_deg[d4.x], 1);
        atomicAdd(&g_deg[d4.y], 1);
        atomicAdd(&g_deg[d4.z], 1);
        atomicAdd(&g_deg[d4.w], 1);
    } else {
        for (int i = base; i < e; i++) atomicAdd(&g_deg[dst[i]], 1);
    }
}
__global__ void count_deg_scalar_kernel(const int* __restrict__ dst, int e) {
    int i = blockIdx.x * blockDim.x + threadIdx.x;
    if (i < e) atomicAdd(&g_deg[dst[i]], 1);
}

// ---------------- scanA: per-chunk exclusive scan (coalesced smem staging) ----------------
__global__ void scanA_kernel(int n) {
    __shared__ int sdeg[CHUNK];
    __shared__ int wsum[8], woff[8];
    int t = threadIdx.x;
    int c0 = blockIdx.x * CHUNK;
    #pragma unroll
    for (int r = 0; r < CHUNK / 256; r++) {
        int idx = t + r * 256;
        int node = c0 + idx;
        sdeg[idx] = (node < n) ? g_deg[node] : 0;
    }
    __syncthreads();
    int s = 0;
    #pragma unroll
    for (int r = 0; r < 8; r++) s += sdeg[t * 8 + r];
    int lane = t & 31, wid = t >> 5;
    int incl = s;
    #pragma unroll
    for (int off = 1; off < 32; off <<= 1) {
        int v = __shfl_up_sync(0xffffffffu, incl, off);
        if (lane >= off) incl += v;
    }
    if (lane == 31) wsum[wid] = incl;
    __syncthreads();
    if (t < 8) {
        int acc = 0;
        for (int w = 0; w < t; w++) acc += wsum[w];
        woff[t] = acc;
    }
    __syncthreads();
    int run = incl - s + woff[wid];
    #pragma unroll
    for (int r = 0; r < 8; r++) {
        int node = c0 + t * 8 + r;
        if (node < n) { g_rowoff[node] = run; run += sdeg[t * 8 + r]; }
    }
    if (t == 255) g_csum[blockIdx.x] = incl + woff[wid];
}

// scanC: warp-scan chunk offsets + apply + dinv + cursor
__global__ void scanC_kernel(int n, int nchunks) {
    __shared__ int coff[NCHUNKS + 32];
    int t = threadIdx.x;
    if (t < 32) {
        int acc = 0;
        for (int b0 = 0; b0 < nchunks; b0 += 32) {
            int idx = b0 + t;
            int v = (idx < nchunks) ? g_csum[idx] : 0;
            int incl = v;
            #pragma unroll
            for (int off = 1; off < 32; off <<= 1) {
                int u = __shfl_up_sync(0xffffffffu, incl, off);
                if (t >= off) incl += u;
            }
            if (idx < nchunks) coff[idx] = acc + incl - v;
            int tot = __shfl_sync(0xffffffffu, incl, 31);
            acc += tot;
        }
    }
    __syncthreads();
    int i = blockIdx.x * blockDim.x + t;
    if (i >= n) return;
    int off = g_rowoff[i] + coff[i / CHUNK];
    g_rowoff[i] = off;
    g_cursor[i] = off;
    g_dinv[i] = rsqrtf((float)(g_deg[i] + 1)); // +1 self-loop
}

// ======= merged scatter (4/5 blocks) + gemm (1/5 blocks, register form, no smem) =======
// gemm: tmpA = (x @ W1) * dinv    scatter: csr[cursor[dst]++] = src
__global__ void __launch_bounds__(128)
scatter_gemm_kernel(const int* __restrict__ src, const int* __restrict__ dst,
                    const float* __restrict__ x, const float* __restrict__ W,
                    int n, int e) {
    int bid = blockIdx.x;
    int t = threadIdx.x;
    int r5 = bid % 5;

    if (r5 != 0) {
        // ---- scatter role: one int4 quad per thread ----
        int cidx = (bid / 5) * 4 + (r5 - 1);
        int quads = e >> 2;
        int q = cidx * 128 + t;
        if (q < quads) {
            int base = q * 4;
            int4 s4 = *(const int4*)(src + base);
            int4 d4 = *(const int4*)(dst + base);
            int p;
            p = atomicAdd(&g_cursor[d4.x], 1); g_csr[p] = s4.x;
            p = atomicAdd(&g_cursor[d4.y], 1); g_csr[p] = s4.y;
            p = atomicAdd(&g_cursor[d4.z], 1); g_csr[p] = s4.z;
            p = atomicAdd(&g_cursor[d4.w], 1); g_csr[p] = s4.w;
        }
        if (cidx == 0 && t == 0)
            for (int i = quads * 4; i < e; i++) {
                int p = atomicAdd(&g_cursor[dst[i]], 1);
                g_csr[p] = src[i];
            }
        return;
    }

    // ---- gemm role: warp per node, W in registers, shuffle reduce ----
    int lane = t & 31;
    float4 w0 = *(const float4*)(W + (lane * 4 + 0) * 4);
    float4 w1 = *(const float4*)(W + (lane * 4 + 1) * 4);
    float4 w2 = *(const float4*)(W + (lane * 4 + 2) * 4);
    float4 w3 = *(const float4*)(W + (lane * 4 + 3) * 4);

    int gblk = bid / 5;
    int gwarp = gblk * 4 + (t >> 5);
    int nwarps = (gridDim.x / 5 + (gridDim.x % 5 ? 1 : 0)) * 4;  // gemm blocks × 4
    // exact gemm block count = ceil(gridDim.x / 5) since r5==0 blocks are bid=0,5,10,...
    for (int node = gwarp; node < n; node += nwarps) {
        float4 xv = *(const float4*)(x + (size_t)node * 128 + lane * 4);
        float a0 = xv.x * w0.x + xv.y * w1.x + xv.z * w2.x + xv.w * w3.x;
        float a1 = xv.x * w0.y + xv.y * w1.y + xv.z * w2.y + xv.w * w3.y;
        float a2 = xv.x * w0.z + xv.y * w1.z + xv.z * w2.z + xv.w * w3.z;
        float a3 = xv.x * w0.w + xv.y * w1.w + xv.z * w2.w + xv.w * w3.w;
        #pragma unroll
        for (int off = 16; off > 0; off >>= 1) {
            a0 += __shfl_down_sync(0xffffffffu, a0, off);
            a1 += __shfl_down_sync(0xffffffffu, a1, off);
            a2 += __shfl_down_sync(0xffffffffu, a2, off);
            a3 += __shfl_down_sync(0xffffffffu, a3, off);
        }
        if (lane == 0) {
            float dv = g_dinv[node];
            *(float4*)(g_tmpA + (size_t)node * 4) =
                make_float4(a0 * dv, a1 * dv, a2 * dv, a3 * dv);
        }
    }
}

// fallbacks (misaligned edge array): plain scatter + plain gemm
__global__ void scatter_scalar_kernel(const int* __restrict__ src, const int* __restrict__ dst, int e) {
    int i = blockIdx.x * blockDim.x + threadIdx.x;
    if (i >= e) return;
    int p = atomicAdd(&g_cursor[dst[i]], 1);
    g_csr[p] = src[i];
}
__global__ void gemm1_plain_kernel(const float* __restrict__ x, const float* __restrict__ W, int n) {
    int lane = threadIdx.x & 31;
    float4 w0 = *(const float4*)(W + (lane * 4 + 0) * 4);
    float4 w1 = *(const float4*)(W + (lane * 4 + 1) * 4);
    float4 w2 = *(const float4*)(W + (lane * 4 + 2) * 4);
    float4 w3 = *(const float4*)(W + (lane * 4 + 3) * 4);
    int gwarp = (blockIdx.x * blockDim.x + threadIdx.x) >> 5;
    int nwarps = (gridDim.x * blockDim.x) >> 5;
    for (int node = gwarp; node < n; node += nwarps) {
        float4 xv = *(const float4*)(x + (size_t)node * 128 + lane * 4);
        float a0 = xv.x * w0.x + xv.y * w1.x + xv.z * w2.x + xv.w * w3.x;
        float a1 = xv.x * w0.y + xv.y * w1.y + xv.z * w2.y + xv.w * w3.y;
        float a2 = xv.x * w0.z + xv.y * w1.z + xv.z * w2.z + xv.w * w3.z;
        float a3 = xv.x * w0.w + xv.y * w1.w + xv.z * w2.w + xv.w * w3.w;
        #pragma unroll
        for (int off = 16; off > 0; off >>= 1) {
            a0 += __shfl_down_sync(0xffffffffu, a0, off);
            a1 += __shfl_down_sync(0xffffffffu, a1, off);
            a2 += __shfl_down_sync(0xffffffffu, a2, off);
            a3 += __shfl_down_sync(0xffffffffu, a3, off);
        }
        if (lane == 0) {
            float dv = g_dinv[node];
            *(float4*)(g_tmpA + (size_t)node * 4) =
                make_float4(a0 * dv, a1 * dv, a2 * dv, a3 * dv);
        }
    }
}

// ========= fused pull (FIN=4): unroll 8, high occupancy =========
template <int FNEXT>
__global__ void __launch_bounds__(256, 6)
pull4_kernel(const float* __restrict__ tin,
             const float* __restrict__ b,
             const float* __restrict__ Wn,
             float* __restrict__ tout, int n) {
    int i = blockIdx.x * blockDim.x + threadIdx.x;
    if (i >= n) return;
    const float4* tp = (const float4*)tin;
    float4 a0 = tp[i];  // self-loop term (prescaled)
    float4 a1 = make_float4(0.f, 0.f, 0.f, 0.f), a2 = a1, a3 = a1;
    int j = g_rowoff[i];
    int jend = j + g_deg[i];
    for (; j + 8 <= jend; j += 8) {
        int s0 = __ldg(&g_csr[j]),     s1 = __ldg(&g_csr[j + 1]);
        int s2 = __ldg(&g_csr[j + 2]), s3 = __ldg(&g_csr[j + 3]);
        int s4 = __ldg(&g_csr[j + 4]), s5 = __ldg(&g_csr[j + 5]);
        int s6 = __ldg(&g_csr[j + 6]), s7 = __ldg(&g_csr[j + 7]);
        float4 v0 = tp[s0], v1 = tp[s1], v2 = tp[s2], v3 = tp[s3];
        float4 v4 = tp[s4], v5 = tp[s5], v6 = tp[s6], v7 = tp[s7];
        a0.x += v0.x; a0.y += v0.y; a0.z += v0.z; a0.w += v0.w;
        a1.x += v1.x; a1.y += v1.y; a1.z += v1.z; a1.w += v1.w;
        a2.x += v2.x; a2.y += v2.y; a2.z += v2.z; a2.w += v2.w;
        a3.x += v3.x; a3.y += v3.y; a3.z += v3.z; a3.w += v3.w;
        a0.x += v4.x; a0.y += v4.y; a0.z += v4.z; a0.w += v4.w;
        a1.x += v5.x; a1.y += v5.y; a1.z += v5.z; a1.w += v5.w;
        a2.x += v6.x; a2.y += v6.y; a2.z += v6.z; a2.w += v6.w;
        a3.x += v7.x; a3.y += v7.y; a3.z += v7.z; a3.w += v7.w;
    }
    for (; j < jend; j++) {
        float4 v = tp[__ldg(&g_csr[j])];
        a0.x += v.x; a0.y += v.y; a0.z += v.z; a0.w += v.w;
    }
    float dv = g_dinv[i];
    float sx = (a0.x + a1.x) + (a2.x + a3.x);
    float sy = (a0.y + a1.y) + (a2.y + a3.y);
    float sz = (a0.z + a1.z) + (a2.z + a3.z);
    float sw = (a0.w + a1.w) + (a2.w + a3.w);
    float h0 = tanhf(sx * dv + __ldg(&b[0]));
    float h1 = tanhf(sy * dv + __ldg(&b[1]));
    float h2 = tanhf(sz * dv + __ldg(&b[2]));
    float h3 = tanhf(sw * dv + __ldg(&b[3]));
    if (FNEXT == 4) {
        float4 o;
        o.x = (h0*__ldg(&Wn[0*4+0]) + h1*__ldg(&Wn[1*4+0]) + h2*__ldg(&Wn[2*4+0]) + h3*__ldg(&Wn[3*4+0])) * dv;
        o.y = (h0*__ldg(&Wn[0*4+1]) + h1*__ldg(&Wn[1*4+1]) + h2*__ldg(&Wn[2*4+1]) + h3*__ldg(&Wn[3*4+1])) * dv;
        o.z = (h0*__ldg(&Wn[0*4+2]) + h1*__ldg(&Wn[1*4+2]) + h2*__ldg(&Wn[2*4+2]) + h3*__ldg(&Wn[3*4+2])) * dv;
        o.w = (h0*__ldg(&Wn[0*4+3]) + h1*__ldg(&Wn[1*4+3]) + h2*__ldg(&Wn[2*4+3]) + h3*__ldg(&Wn[3*4+3])) * dv;
        *(float4*)(tout + (size_t)i * 4) = o;
    } else {
        float2 o;
        o.x = (h0*__ldg(&Wn[0*2+0]) + h1*__ldg(&Wn[1*2+0]) + h2*__ldg(&Wn[2*2+0]) + h3*__ldg(&Wn[3*2+0])) * dv;
        o.y = (h0*__ldg(&Wn[0*2+1]) + h1*__ldg(&Wn[1*2+1]) + h2*__ldg(&Wn[2*2+1]) + h3*__ldg(&Wn[3*2+1])) * dv;
        *(float2*)(tout + (size_t)i * 2) = o;
    }
}

// ========= fused pull (FIN=2) + classifier + outputs =========
__global__ void __launch_bounds__(256, 6)
pull2_cls_kernel(const float* __restrict__ tin,
                 const float* __restrict__ b3,
                 const float* __restrict__ Wc,
                 const float* __restrict__ bc,
                 float* __restrict__ out,
                 float* __restrict__ hsec, int n) {
    int i = blockIdx.x * blockDim.x + threadIdx.x;
    if (i >= n) return;
    const float2* tp = (const float2*)tin;
    float2 a0 = tp[i];
    float2 a1 = make_float2(0.f, 0.f), a2 = a1, a3 = a1;
    int j = g_rowoff[i];
    int jend = j + g_deg[i];
    for (; j + 8 <= jend; j += 8) {
        int s0 = __ldg(&g_csr[j]),     s1 = __ldg(&g_csr[j + 1]);
        int s2 = __ldg(&g_csr[j + 2]), s3 = __ldg(&g_csr[j + 3]);
        int s4 = __ldg(&g_csr[j + 4]), s5 = __ldg(&g_csr[j + 5]);
        int s6 = __ldg(&g_csr[j + 6]), s7 = __ldg(&g_csr[j + 7]);
        float2 v0 = tp[s0], v1 = tp[s1], v2 = tp[s2], v3 = tp[s3];
        float2 v4 = tp[s4], v5 = tp[s5], v6 = tp[s6], v7 = tp[s7];
        a0.x += v0.x; a0.y += v0.y;
        a1.x += v1.x; a1.y += v1.y;
        a2.x += v2.x; a2.y += v2.y;
        a3.x += v3.x; a3.y += v3.y;
        a0.x += v4.x; a0.y += v4.y;
        a1.x += v5.x; a1.y += v5.y;
        a2.x += v6.x; a2.y += v6.y;
        a3.x += v7.x; a3.y += v7.y;
    }
    for (; j < jend; j++) {
        float2 v = tp[__ldg(&g_csr[j])];
        a0.x += v.x; a0.y += v.y;
    }
    float dv = g_dinv[i];
    float sx = (a0.x + a1.x) + (a2.x + a3.x);
    float sy = (a0.y + a1.y) + (a2.y + a3.y);
    float h0 = tanhf(sx * dv + __ldg(&b3[0]));
    float h1 = tanhf(sy * dv + __ldg(&b3[1]));
    *(float2*)(hsec + (size_t)i * 2) = make_float2(h0, h1);
    #pragma unroll
    for (int j0 = 0; j0 < 16; j0 += 4) {
        float4 v;
        v.x = h0*__ldg(&Wc[0*16+j0+0]) + h1*__ldg(&Wc[1*16+j0+0]) + __ldg(&bc[j0+0]);
        v.y = h0*__ldg(&Wc[0*16+j0+1]) + h1*__ldg(&Wc[1*16+j0+1]) + __ldg(&bc[j0+1]);
        v.z = h0*__ldg(&Wc[0*16+j0+2]) + h1*__ldg(&Wc[1*16+j0+2]) + __ldg(&bc[j0+2]);
        v.w = h0*__ldg(&Wc[0*16+j0+3]) + h1*__ldg(&Wc[1*16+j0+3]) + __ldg(&bc[j0+3]);
        *(float4*)(out + (size_t)i * 16 + j0) = v;
    }
}

extern "C" void kernel_launch(void* const* d_in, const int* in_sizes, int n_in,
                              void* d_out, int out_size) {
    const float* x  = (const float*)d_in[0];
    const float* W1 = (const float*)d_in[1];
    const float* b1 = (const float*)d_in[2];
    const float* W2 = (const float*)d_in[3];
    const float* b2 = (const float*)d_in[4];
    const float* W3 = (const float*)d_in[5];
    const float* b3 = (const float*)d_in[6];
    const float* Wc = (const float*)d_in[7];
    const float* bc = (const float*)d_in[8];
    const int*   ei = (const int*)d_in[9];

    const int n = in_sizes[0] / 128;
    const int e = in_sizes[9] / 2;
    const int* src = ei;
    const int* dst = ei + e;

    const int B = 256;
    const bool vec = ((e & 3) == 0) &&
                     ((((unsigned long long)(uintptr_t)dst) & 15ull) == 0) &&
                     ((((unsigned long long)(uintptr_t)src) & 15ull) == 0);

    int*   deg_p;  cudaGetSymbolAddress((void**)&deg_p, g_deg);
    float* tmpA;   cudaGetSymbolAddress((void**)&tmpA, g_tmpA);
    float* tmpB;   cudaGetSymbolAddress((void**)&tmpB, g_tmpB);
    float* tmpC;   cudaGetSymbolAddress((void**)&tmpC, g_tmpC);

    cudaMemsetAsync(deg_p, 0, (size_t)n * sizeof(int));

    // count standalone (full grid, no smem cap)
    if (vec) count_deg_kernel<<<cdiv(cdiv(e, 4), B), B>>>(dst, e);
    else     count_deg_scalar_kernel<<<cdiv(e, B), B>>>(dst, e);

    scanA_kernel<<<cdiv(n, CHUNK), 256>>>(n);
    scanC_kernel<<<cdiv(n, B), B>>>(n, cdiv(n, CHUNK));

    // scatter (4/5) + gemm (1/5) merged — gemm hides under scatter's L2-bound shadow
    if (vec) {
        int quads = e >> 2;
        int SB = cdiv(quads, 128);            // scatter blocks needed
        int T = cdiv(SB, 4) * 5;              // 1 gemm block per 4 scatter blocks
        scatter_gemm_kernel<<<T, 128>>>(src, dst, x, W1, n, e);
    } else {
        scatter_scalar_kernel<<<cdiv(e, B), B>>>(src, dst, e);
        gemm1_plain_kernel<<<1184, B>>>(x, W1, n);
    }

    pull4_kernel<4><<<cdiv(n, B), B>>>(tmpA, b1, W2, tmpB, n);
    pull4_kernel<2><<<cdiv(n, B), B>>>(tmpB, b2, W3, tmpC, n);

    float* out  = (float*)d_out;
    float* hsec = out + (size_t)n * 16;
    pull2_cls_kernel<<<cdiv(n, B), B>>>(tmpC, b3, Wc, bc, out, hsec, n);
}

// round 17
// speedup vs baseline: 1.1013x; 1.0719x over previous
#include <cuda_runtime.h>
#include <cstdint>

#define NMAX 200000
#define EMAX 6400000
#define CHUNK 2048
#define NCHUNKS ((NMAX + CHUNK - 1) / CHUNK)   // 98

// Scratch (device globals — no allocation allowed)
__device__ int g_deg[NMAX];
__device__ int g_rowoff[NMAX];
__device__ int g_cursor[NMAX];
__device__ int g_csum[NCHUNKS];
__device__ int g_csr[EMAX];
__device__ __align__(16) float g_dinv[NMAX];
__device__ __align__(16) float g_tmpA[NMAX * 4];
__device__ __align__(16) float g_tmpB[NMAX * 4];
__device__ __align__(16) float g_tmpC[NMAX * 2];

static inline int cdiv(int a, int b) { return (a + b - 1) / b; }

// ---------------- count: full grid, 4 edges/thread ----------------
__global__ void count_deg_kernel(const int* __restrict__ dst, int e) {
    int t = blockIdx.x * blockDim.x + threadIdx.x;
    int base = t * 4;
    if (base >= e) return;
    if (base + 4 <= e) {
        int4 d4 = *(const int4*)(dst + base);
        atomicAdd(&g_deg[d4.x], 1);
        atomicAdd(&g_deg[d4.y], 1);
        atomicAdd(&g_deg[d4.z], 1);
        atomicAdd(&g_deg[d4.w], 1);
    } else {
        for (int i = base; i < e; i++) atomicAdd(&g_deg[dst[i]], 1);
    }
}
__global__ void count_deg_scalar_kernel(const int* __restrict__ dst, int e) {
    int i = blockIdx.x * blockDim.x + threadIdx.x;
    if (i < e) atomicAdd(&g_deg[dst[i]], 1);
}

// ---------------- scanA: per-chunk exclusive scan (coalesced smem staging) ----------------
__global__ void scanA_kernel(int n) {
    __shared__ int sdeg[CHUNK];
    __shared__ int wsum[8], woff[8];
    int t = threadIdx.x;
    int c0 = blockIdx.x * CHUNK;
    #pragma unroll
    for (int r = 0; r < CHUNK / 256; r++) {
        int idx = t + r * 256;
        int node = c0 + idx;
        sdeg[idx] = (node < n) ? g_deg[node] : 0;
    }
    __syncthreads();
    int s = 0;
    #pragma unroll
    for (int r = 0; r < 8; r++) s += sdeg[t * 8 + r];
    int lane = t & 31, wid = t >> 5;
    int incl = s;
    #pragma unroll
    for (int off = 1; off < 32; off <<= 1) {
        int v = __shfl_up_sync(0xffffffffu, incl, off);
        if (lane >= off) incl += v;
    }
    if (lane == 31) wsum[wid] = incl;
    __syncthreads();
    if (t < 8) {
        int acc = 0;
        for (int w = 0; w < t; w++) acc += wsum[w];
        woff[t] = acc;
    }
    __syncthreads();
    int run = incl - s + woff[wid];
    #pragma unroll
    for (int r = 0; r < 8; r++) {
        int node = c0 + t * 8 + r;
        if (node < n) { g_rowoff[node] = run; run += sdeg[t * 8 + r]; }
    }
    if (t == 255) g_csum[blockIdx.x] = incl + woff[wid];
}

// scanC: warp-scan chunk offsets + apply + dinv + cursor
__global__ void scanC_kernel(int n, int nchunks) {
    __shared__ int coff[NCHUNKS + 32];
    int t = threadIdx.x;
    if (t < 32) {
        int acc = 0;
        for (int b0 = 0; b0 < nchunks; b0 += 32) {
            int idx = b0 + t;
            int v = (idx < nchunks) ? g_csum[idx] : 0;
            int incl = v;
            #pragma unroll
            for (int off = 1; off < 32; off <<= 1) {
                int u = __shfl_up_sync(0xffffffffu, incl, off);
                if (t >= off) incl += u;
            }
            if (idx < nchunks) coff[idx] = acc + incl - v;
            int tot = __shfl_sync(0xffffffffu, incl, 31);
            acc += tot;
        }
    }
    __syncthreads();
    int i = blockIdx.x * blockDim.x + t;
    if (i >= n) return;
    int off = g_rowoff[i] + coff[i / CHUNK];
    g_rowoff[i] = off;
    g_cursor[i] = off;
    g_dinv[i] = rsqrtf((float)(g_deg[i] + 1)); // +1 self-loop
}

// ======= merged scatter (4/5 blocks) + gemm (1/5 blocks, register form) =======
__global__ void __launch_bounds__(128)
scatter_gemm_kernel(const int* __restrict__ src, const int* __restrict__ dst,
                    const float* __restrict__ x, const float* __restrict__ W,
                    int n, int e) {
    int bid = blockIdx.x;
    int t = threadIdx.x;
    int r5 = bid % 5;

    if (r5 != 0) {
        int cidx = (bid / 5) * 4 + (r5 - 1);
        int quads = e >> 2;
        int q = cidx * 128 + t;
        if (q < quads) {
            int base = q * 4;
            int4 s4 = *(const int4*)(src + base);
            int4 d4 = *(const int4*)(dst + base);
            int p;
            p = atomicAdd(&g_cursor[d4.x], 1); g_csr[p] = s4.x;
            p = atomicAdd(&g_cursor[d4.y], 1); g_csr[p] = s4.y;
            p = atomicAdd(&g_cursor[d4.z], 1); g_csr[p] = s4.z;
            p = atomicAdd(&g_cursor[d4.w], 1); g_csr[p] = s4.w;
        }
        if (cidx == 0 && t == 0)
            for (int i = quads * 4; i < e; i++) {
                int p = atomicAdd(&g_cursor[dst[i]], 1);
                g_csr[p] = src[i];
            }
        return;
    }

    int lane = t & 31;
    float4 w0 = *(const float4*)(W + (lane * 4 + 0) * 4);
    float4 w1 = *(const float4*)(W + (lane * 4 + 1) * 4);
    float4 w2 = *(const float4*)(W + (lane * 4 + 2) * 4);
    float4 w3 = *(const float4*)(W + (lane * 4 + 3) * 4);

    int gblk = bid / 5;
    int gwarp = gblk * 4 + (t >> 5);
    int nwarps = (gridDim.x / 5 + (gridDim.x % 5 ? 1 : 0)) * 4;
    for (int node = gwarp; node < n; node += nwarps) {
        float4 xv = *(const float4*)(x + (size_t)node * 128 + lane * 4);
        float a0 = xv.x * w0.x + xv.y * w1.x + xv.z * w2.x + xv.w * w3.x;
        float a1 = xv.x * w0.y + xv.y * w1.y + xv.z * w2.y + xv.w * w3.y;
        float a2 = xv.x * w0.z + xv.y * w1.z + xv.z * w2.z + xv.w * w3.z;
        float a3 = xv.x * w0.w + xv.y * w1.w + xv.z * w2.w + xv.w * w3.w;
        #pragma unroll
        for (int off = 16; off > 0; off >>= 1) {
            a0 += __shfl_down_sync(0xffffffffu, a0, off);
            a1 += __shfl_down_sync(0xffffffffu, a1, off);
            a2 += __shfl_down_sync(0xffffffffu, a2, off);
            a3 += __shfl_down_sync(0xffffffffu, a3, off);
        }
        if (lane == 0) {
            float dv = g_dinv[node];
            *(float4*)(g_tmpA + (size_t)node * 4) =
                make_float4(a0 * dv, a1 * dv, a2 * dv, a3 * dv);
        }
    }
}

// fallbacks (misaligned edge array)
__global__ void scatter_scalar_kernel(const int* __restrict__ src, const int* __restrict__ dst, int e) {
    int i = blockIdx.x * blockDim.x + threadIdx.x;
    if (i >= e) return;
    int p = atomicAdd(&g_cursor[dst[i]], 1);
    g_csr[p] = src[i];
}
__global__ void gemm1_plain_kernel(const float* __restrict__ x, const float* __restrict__ W, int n) {
    int lane = threadIdx.x & 31;
    float4 w0 = *(const float4*)(W + (lane * 4 + 0) * 4);
    float4 w1 = *(const float4*)(W + (lane * 4 + 1) * 4);
    float4 w2 = *(const float4*)(W + (lane * 4 + 2) * 4);
    float4 w3 = *(const float4*)(W + (lane * 4 + 3) * 4);
    int gwarp = (blockIdx.x * blockDim.x + threadIdx.x) >> 5;
    int nwarps = (gridDim.x * blockDim.x) >> 5;
    for (int node = gwarp; node < n; node += nwarps) {
        float4 xv = *(const float4*)(x + (size_t)node * 128 + lane * 4);
        float a0 = xv.x * w0.x + xv.y * w1.x + xv.z * w2.x + xv.w * w3.x;
        float a1 = xv.x * w0.y + xv.y * w1.y + xv.z * w2.y + xv.w * w3.y;
        float a2 = xv.x * w0.z + xv.y * w1.z + xv.z * w2.z + xv.w * w3.z;
        float a3 = xv.x * w0.w + xv.y * w1.w + xv.z * w2.w + xv.w * w3.w;
        #pragma unroll
        for (int off = 16; off > 0; off >>= 1) {
            a0 += __shfl_down_sync(0xffffffffu, a0, off);
            a1 += __shfl_down_sync(0xffffffffu, a1, off);
            a2 += __shfl_down_sync(0xffffffffu, a2, off);
            a3 += __shfl_down_sync(0xffffffffu, a3, off);
        }
        if (lane == 0) {
            float dv = g_dinv[node];
            *(float4*)(g_tmpA + (size_t)node * 4) =
                make_float4(a0 * dv, a1 * dv, a2 * dv, a3 * dv);
        }
    }
}

// ========= edge-balanced pull (FIN=4): 8 threads/node, shuffle reduce =========
template <int FNEXT>
__global__ void __launch_bounds__(256, 6)
pull4_kernel(const float* __restrict__ tin,
             const float* __restrict__ b,
             const float* __restrict__ Wn,
             float* __restrict__ tout, int n) {
    int gid = blockIdx.x * blockDim.x + threadIdx.x;
    int node = gid >> 3;
    int sub = gid & 7;
    bool valid = (node < n);
    const float4* tp = (const float4*)tin;

    float4 a0 = make_float4(0.f, 0.f, 0.f, 0.f), a1 = a0;
    int row = 0, deg = 0;
    if (valid) {
        row = g_rowoff[node];
        deg = g_deg[node];
        if (sub == 0) a0 = tp[node];   // self-loop (prescaled)
    }
    int j = row + sub;
    int jend = row + deg;
    // unroll 2: two independent gathers in flight per thread
    for (; j + 8 < jend; j += 16) {
        int s0 = __ldg(&g_csr[j]);
        int s1 = __ldg(&g_csr[j + 8]);
        float4 v0 = tp[s0], v1 = tp[s1];
        a0.x += v0.x; a0.y += v0.y; a0.z += v0.z; a0.w += v0.w;
        a1.x += v1.x; a1.y += v1.y; a1.z += v1.z; a1.w += v1.w;
    }
    if (j < jend) {
        float4 v = tp[__ldg(&g_csr[j])];
        a0.x += v.x; a0.y += v.y; a0.z += v.z; a0.w += v.w;
    }
    a0.x += a1.x; a0.y += a1.y; a0.z += a1.z; a0.w += a1.w;
    // reduce across the 8-lane group
    #pragma unroll
    for (int off = 4; off > 0; off >>= 1) {
        a0.x += __shfl_down_sync(0xffffffffu, a0.x, off, 8);
        a0.y += __shfl_down_sync(0xffffffffu, a0.y, off, 8);
        a0.z += __shfl_down_sync(0xffffffffu, a0.z, off, 8);
        a0.w += __shfl_down_sync(0xffffffffu, a0.w, off, 8);
    }
    if (valid && sub == 0) {
        float dv = g_dinv[node];
        float h0 = tanhf(a0.x * dv + __ldg(&b[0]));
        float h1 = tanhf(a0.y * dv + __ldg(&b[1]));
        float h2 = tanhf(a0.z * dv + __ldg(&b[2]));
        float h3 = tanhf(a0.w * dv + __ldg(&b[3]));
        if (FNEXT == 4) {
            float4 o;
            o.x = (h0*__ldg(&Wn[0*4+0]) + h1*__ldg(&Wn[1*4+0]) + h2*__ldg(&Wn[2*4+0]) + h3*__ldg(&Wn[3*4+0])) * dv;
            o.y = (h0*__ldg(&Wn[0*4+1]) + h1*__ldg(&Wn[1*4+1]) + h2*__ldg(&Wn[2*4+1]) + h3*__ldg(&Wn[3*4+1])) * dv;
            o.z = (h0*__ldg(&Wn[0*4+2]) + h1*__ldg(&Wn[1*4+2]) + h2*__ldg(&Wn[2*4+2]) + h3*__ldg(&Wn[3*4+2])) * dv;
            o.w = (h0*__ldg(&Wn[0*4+3]) + h1*__ldg(&Wn[1*4+3]) + h2*__ldg(&Wn[2*4+3]) + h3*__ldg(&Wn[3*4+3])) * dv;
            *(float4*)(tout + (size_t)node * 4) = o;
        } else {
            float2 o;
            o.x = (h0*__ldg(&Wn[0*2+0]) + h1*__ldg(&Wn[1*2+0]) + h2*__ldg(&Wn[2*2+0]) + h3*__ldg(&Wn[3*2+0])) * dv;
            o.y = (h0*__ldg(&Wn[0*2+1]) + h1*__ldg(&Wn[1*2+1]) + h2*__ldg(&Wn[2*2+1]) + h3*__ldg(&Wn[3*2+1])) * dv;
            *(float2*)(tout + (size_t)node * 2) = o;
        }
    }
}

// ========= edge-balanced pull (FIN=2) + classifier + outputs =========
__global__ void __launch_bounds__(256, 6)
pull2_cls_kernel(const float* __restrict__ tin,
                 const float* __restrict__ b3,
                 const float* __restrict__ Wc,
                 const float* __restrict__ bc,
                 float* __restrict__ out,
                 float* __restrict__ hsec, int n) {
    int gid = blockIdx.x * blockDim.x + threadIdx.x;
    int node = gid >> 3;
    int sub = gid & 7;
    bool valid = (node < n);
    const float2* tp = (const float2*)tin;

    float2 a0 = make_float2(0.f, 0.f), a1 = a0;
    int row = 0, deg = 0;
    if (valid) {
        row = g_rowoff[node];
        deg = g_deg[node];
        if (sub == 0) a0 = tp[node];
    }
    int j = row + sub;
    int jend = row + deg;
    for (; j + 8 < jend; j += 16) {
        int s0 = __ldg(&g_csr[j]);
        int s1 = __ldg(&g_csr[j + 8]);
        float2 v0 = tp[s0], v1 = tp[s1];
        a0.x += v0.x; a0.y += v0.y;
        a1.x += v1.x; a1.y += v1.y;
    }
    if (j < jend) {
        float2 v = tp[__ldg(&g_csr[j])];
        a0.x += v.x; a0.y += v.y;
    }
    a0.x += a1.x; a0.y += a1.y;
    #pragma unroll
    for (int off = 4; off > 0; off >>= 1) {
        a0.x += __shfl_down_sync(0xffffffffu, a0.x, off, 8);
        a0.y += __shfl_down_sync(0xffffffffu, a0.y, off, 8);
    }
    // lane 0 computes h; broadcast to the 8-lane group
    float h0 = 0.f, h1 = 0.f;
    if (sub == 0) {
        float dv = (valid) ? g_dinv[node] : 0.f;
        h0 = tanhf(a0.x * dv + __ldg(&b3[0]));
        h1 = tanhf(a0.y * dv + __ldg(&b3[1]));
    }
    h0 = __shfl_sync(0xffffffffu, h0, 0, 8);
    h1 = __shfl_sync(0xffffffffu, h1, 0, 8);
    if (valid) {
        if (sub == 0)
            *(float2*)(hsec + (size_t)node * 2) = make_float2(h0, h1);
        // 8 lanes write 2 classes each (coalesced float2 stores)
        int c = sub * 2;
        float2 v;
        v.x = h0*__ldg(&Wc[0*16 + c])     + h1*__ldg(&Wc[1*16 + c])     + __ldg(&bc[c]);
        v.y = h0*__ldg(&Wc[0*16 + c + 1]) + h1*__ldg(&Wc[1*16 + c + 1]) + __ldg(&bc[c + 1]);
        *(float2*)(out + (size_t)node * 16 + c) = v;
    }
}

extern "C" void kernel_launch(void* const* d_in, const int* in_sizes, int n_in,
                              void* d_out, int out_size) {
    const float* x  = (const float*)d_in[0];
    const float* W1 = (const float*)d_in[1];
    const float* b1 = (const float*)d_in[2];
    const float* W2 = (const float*)d_in[3];
    const float* b2 = (const float*)d_in[4];
    const float* W3 = (const float*)d_in[5];
    const float* b3 = (const float*)d_in[6];
    const float* Wc = (const float*)d_in[7];
    const float* bc = (const float*)d_in[8];
    const int*   ei = (const int*)d_in[9];

    const int n = in_sizes[0] / 128;
    const int e = in_sizes[9] / 2;
    const int* src = ei;
    const int* dst = ei + e;

    const int B = 256;
    const bool vec = ((e & 3) == 0) &&
                     ((((unsigned long long)(uintptr_t)dst) & 15ull) == 0) &&
                     ((((unsigned long long)(uintptr_t)src) & 15ull) == 0);

    int*   deg_p;  cudaGetSymbolAddress((void**)&deg_p, g_deg);
    float* tmpA;   cudaGetSymbolAddress((void**)&tmpA, g_tmpA);
    float* tmpB;   cudaGetSymbolAddress((void**)&tmpB, g_tmpB);
    float* tmpC;   cudaGetSymbolAddress((void**)&tmpC, g_tmpC);

    cudaMemsetAsync(deg_p, 0, (size_t)n * sizeof(int));

    if (vec) count_deg_kernel<<<cdiv(cdiv(e, 4), B), B>>>(dst, e);
    else     count_deg_scalar_kernel<<<cdiv(e, B), B>>>(dst, e);

    scanA_kernel<<<cdiv(n, CHUNK), 256>>>(n);
    scanC_kernel<<<cdiv(n, B), B>>>(n, cdiv(n, CHUNK));

    if (vec) {
        int quads = e >> 2;
        int SB = cdiv(quads, 128);
        int T = cdiv(SB, 4) * 5;
        scatter_gemm_kernel<<<T, 128>>>(src, dst, x, W1, n, e);
    } else {
        scatter_scalar_kernel<<<cdiv(e, B), B>>>(src, dst, e);
        gemm1_plain_kernel<<<1184, B>>>(x, W1, n);
    }

    // edge-balanced pulls: 8 threads per node
    pull4_kernel<4><<<cdiv(n * 8, B), B>>>(tmpA, b1, W2, tmpB, n);
    pull4_kernel<2><<<cdiv(n * 8, B), B>>>(tmpB, b2, W3, tmpC, n);

    float* out  = (float*)d_out;
    float* hsec = out + (size_t)n * 16;
    pull2_cls_kernel<<<cdiv(n * 8, B), B>>>(tmpC, b3, Wc, bc, out, hsec, n);
}